// round 1
// baseline (speedup 1.0000x reference)
#include <cuda_runtime.h>

// Problem constants
#define B_  16
#define C_  256
#define M_  4096
#define NSf 65536.0f
#define KD  16
#define UD  4
#define UK  64
#define UV  1024
#define VD  256
#define EPSBN 1e-5f

// ---------------- scratch (device globals; no runtime allocation) ----------------
__device__ float g_G[C_ * C_];          // Gram matrix  X X^T  (atomic-accumulated)
__device__ float g_s[C_];               // column sums of x    (atomic-accumulated)
__device__ float g_Wqk[80 * C_];        // rows 0..15: Wq_eff (BN-folded), 16..79: Wk
__device__ float g_bqk[80];             // matching biases
__device__ float g_WvEff[UV * C_];      // BN-folded Wv
__device__ float g_cb[VD];              // sum_u bv_eff[u,v]  (atomic-accumulated)
__device__ float g_Q[B_ * KD * M_];     // BN'd Q
__device__ float g_P[B_ * UK * M_];     // K logits, then softmax(K)
__device__ float g_T[B_ * UK * C_];     // T = softmax(K) x^T  (atomic-accumulated)
__device__ float g_ctx[B_ * KD * VD];   // context GEMM part   (atomic-accumulated)

// ---------------- k0: zero atomic-accumulated scratch ----------------
__global__ void k0_zero() {
    int i = blockIdx.x * blockDim.x + threadIdx.x;
    int n = blockDim.x * gridDim.x;
    for (int j = i; j < C_ * C_; j += n) g_G[j] = 0.f;
    for (int j = i; j < C_; j += n) { g_s[j] = 0.f; g_cb[j] = 0.f; }
    for (int j = i; j < B_ * UK * C_; j += n) g_T[j] = 0.f;
    for (int j = i; j < B_ * KD * VD; j += n) g_ctx[j] = 0.f;
}

// ---------------- k1: Gram G = X X^T and column sums s ----------------
// grid (4 rowgroups, B_, 4 m-splits), block 256.
// Block computes G[rg*64 .. +64, 0..256) partial over 1024 m-samples of batch b.
__global__ __launch_bounds__(256) void k1_gram(const float* __restrict__ x) {
    __shared__ float sB[C_][33];
    const int rg = blockIdx.x, b = blockIdx.y, ms = blockIdx.z;
    const int tid = threadIdx.x;
    const int ty = tid >> 5, tx = tid & 31;   // rows rg*64 + ty*8 + i ; cols tx + 32*j
    const float* xb = x + (size_t)b * C_ * M_;
    const int m0 = ms * 1024;
    const int r0 = tid >> 5, mm0 = tid & 31;

    float acc[8][8];
#pragma unroll
    for (int i = 0; i < 8; i++)
#pragma unroll
        for (int j = 0; j < 8; j++) acc[i][j] = 0.f;
    float ssum = 0.f;

    for (int mc = 0; mc < 1024; mc += 32) {
        __syncthreads();
#pragma unroll
        for (int i = 0; i < 32; i++) {
            int r = r0 + i * 8;
            sB[r][mm0] = xb[(size_t)r * M_ + m0 + mc + mm0];
        }
        __syncthreads();
        if (rg == 0) {   // column-sum accumulation (row c = tid), done once per (b,m)
#pragma unroll
            for (int mm = 0; mm < 32; mm++) ssum += sB[tid][mm];
        }
#pragma unroll
        for (int mm = 0; mm < 32; mm++) {
            float a[8], bb[8];
#pragma unroll
            for (int i = 0; i < 8; i++) a[i] = sB[rg * 64 + ty * 8 + i][mm];
#pragma unroll
            for (int j = 0; j < 8; j++) bb[j] = sB[tx + 32 * j][mm];
#pragma unroll
            for (int i = 0; i < 8; i++)
#pragma unroll
                for (int j = 0; j < 8; j++) acc[i][j] += a[i] * bb[j];
        }
    }
    if (rg == 0) atomicAdd(&g_s[tid], ssum);
#pragma unroll
    for (int i = 0; i < 8; i++) {
        int r = rg * 64 + ty * 8 + i;
#pragma unroll
        for (int j = 0; j < 8; j++)
            atomicAdd(&g_G[r * C_ + tx + 32 * j], acc[i][j]);
    }
}

// ---------------- k2: BN folding (per-channel quadratic forms) + Wk copy ----------------
// grid 69 blocks of 256.
// blk 0: the 16 Q channels. blk 1..64: V channels (blk-1)*16 .. +16. blk 65..68: copy Wk/bk.
__global__ __launch_bounds__(256) void k2_params(
    const float* __restrict__ Wq, const float* __restrict__ bq,
    const float* __restrict__ Wk, const float* __restrict__ bk,
    const float* __restrict__ Wv, const float* __restrict__ bv,
    const float* __restrict__ gq, const float* __restrict__ btq,
    const float* __restrict__ gv, const float* __restrict__ btv) {
    const int blk = blockIdx.x, tid = threadIdx.x;

    if (blk >= 65) {   // copy raw K weights into the stacked QK weight matrix
        int base = (blk - 65) * 16;
#pragma unroll
        for (int i = 0; i < 16; i++)
            g_Wqk[(16 + base + i) * C_ + tid] = Wk[(base + i) * C_ + tid];
        if (tid < 16) g_bqk[16 + base + tid] = bk[base + tid];
        return;
    }

    __shared__ float w[16][C_];
    __shared__ float qf[16], ds[16], alph[16];
    const bool isQ = (blk == 0);
    const float* Wsrc = isQ ? Wq : (Wv + (size_t)(blk - 1) * 16 * C_);
#pragma unroll
    for (int i = 0; i < 16; i++) w[i][tid] = Wsrc[i * C_ + tid];
    if (tid < 16) { qf[tid] = 0.f; ds[tid] = 0.f; }
    __syncthreads();

    // inner[ch] = sum_r w[ch][r] * G[r, c]  with c = tid
    float inner[16];
#pragma unroll
    for (int ch = 0; ch < 16; ch++) inner[ch] = 0.f;
    const int c = tid;
    for (int r = 0; r < C_; r++) {
        float grc = g_G[r * C_ + c];
#pragma unroll
        for (int ch = 0; ch < 16; ch++) inner[ch] += w[ch][r] * grc;
    }
    const float sc = g_s[c];
    const int lane = tid & 31;
#pragma unroll
    for (int ch = 0; ch < 16; ch++) {
        float vq = inner[ch] * w[ch][c];       // contribution to w^T G w
        float vd = w[ch][c] * sc;              // contribution to w . s
#pragma unroll
        for (int o = 16; o > 0; o >>= 1) {
            vq += __shfl_down_sync(0xffffffffu, vq, o);
            vd += __shfl_down_sync(0xffffffffu, vd, o);
        }
        if (lane == 0) { atomicAdd(&qf[ch], vq); atomicAdd(&ds[ch], vd); }
    }
    __syncthreads();

    if (tid < 16) {
        int ch = tid;
        float bias, gamma, beta;
        if (isQ) { bias = bq[ch]; gamma = gq[ch]; beta = btq[ch]; }
        else {
            int gch = (blk - 1) * 16 + ch;
            bias = bv[gch]; gamma = gv[gch]; beta = btv[gch];
        }
        float dsv  = ds[ch];
        float mean = dsv / NSf + bias;
        float e2   = (qf[ch] + 2.f * bias * dsv) / NSf + bias * bias;
        float var  = e2 - mean * mean;
        float a    = gamma * rsqrtf(var + EPSBN);
        alph[ch]   = a;
        float be   = beta + a * (bias - mean);
        if (isQ) g_bqk[ch] = be;
        else {
            int gch = (blk - 1) * 16 + ch;
            atomicAdd(&g_cb[gch & (VD - 1)], be);   // sum over u of bv_eff[u,v]
        }
    }
    __syncthreads();
#pragma unroll
    for (int i = 0; i < 16; i++) {
        float val = alph[i] * w[i][tid];
        if (isQ) g_Wqk[i * C_ + tid] = val;
        else     g_WvEff[((size_t)(blk - 1) * 16 + i) * C_ + tid] = val;
    }
}

// ---------------- k3: fused Q(BN'd) + K(raw) GEMM ----------------
// out[80, 4096] per b = g_Wqk[80,256] . x_b[256,4096]. grid (32 m-tiles, B_), block 256.
__global__ __launch_bounds__(256) void k3_qk(const float* __restrict__ x) {
    __shared__ float sW[80][33];
    __shared__ float sX[32][129];
    const int mt = blockIdx.x, b = blockIdx.y, tid = threadIdx.x;
    const int ty = tid >> 5, tx = tid & 31;  // rows ty*10 + i (10), cols tx + 32*j (4)
    const float* xb = x + (size_t)b * C_ * M_ + mt * 128;

    float acc[10][4];
#pragma unroll
    for (int i = 0; i < 10; i++)
#pragma unroll
        for (int j = 0; j < 4; j++) acc[i][j] = 0.f;

    const int wr0 = tid >> 5, wc0 = tid & 31;
    const int xr0 = tid >> 7, xc0 = tid & 127;

    for (int kc = 0; kc < C_; kc += 32) {
        __syncthreads();
#pragma unroll
        for (int i = 0; i < 10; i++) {
            int r = wr0 + i * 8;
            sW[r][wc0] = g_Wqk[r * C_ + kc + wc0];
        }
#pragma unroll
        for (int i = 0; i < 16; i++) {
            int kk = xr0 + i * 2;
            sX[kk][xc0] = xb[(size_t)(kc + kk) * M_ + xc0];
        }
        __syncthreads();
#pragma unroll
        for (int kk = 0; kk < 32; kk++) {
            float a[10], bb[4];
#pragma unroll
            for (int i = 0; i < 10; i++) a[i] = sW[ty * 10 + i][kk];
#pragma unroll
            for (int j = 0; j < 4; j++) bb[j] = sX[kk][tx + 32 * j];
#pragma unroll
            for (int i = 0; i < 10; i++)
#pragma unroll
                for (int j = 0; j < 4; j++) acc[i][j] += a[i] * bb[j];
        }
    }
#pragma unroll
    for (int i = 0; i < 10; i++) {
        int r = ty * 10 + i;
        float bias = g_bqk[r];
#pragma unroll
        for (int j = 0; j < 4; j++) {
            int m = mt * 128 + tx + 32 * j;
            float val = acc[i][j] + bias;
            if (r < 16) g_Q[((size_t)b * KD + r) * M_ + m] = val;
            else        g_P[((size_t)b * UK + (r - 16)) * M_ + m] = val;
        }
    }
}

// ---------------- k4: row softmax of K (in place on g_P, normalized) ----------------
// grid B_*UK = 1024 rows, block 256.
__global__ __launch_bounds__(256) void k4_softmax() {
    __shared__ float row[M_ > 0 ? M_ : 1];   // 16 KB
    __shared__ float red[256];
    const int rid = blockIdx.x, tid = threadIdx.x;
    float* p = g_P + (size_t)rid * M_;
    float4* p4 = (float4*)p;
    float4* r4 = (float4*)row;

    float lmax = -3.0e38f;
#pragma unroll
    for (int i = 0; i < 4; i++) {
        float4 v = p4[tid + i * 256];
        r4[tid + i * 256] = v;
        lmax = fmaxf(lmax, fmaxf(fmaxf(v.x, v.y), fmaxf(v.z, v.w)));
    }
    red[tid] = lmax; __syncthreads();
    for (int s = 128; s > 0; s >>= 1) {
        if (tid < s) red[tid] = fmaxf(red[tid], red[tid + s]);
        __syncthreads();
    }
    const float mx = red[0];
    __syncthreads();

    float lsum = 0.f;
#pragma unroll
    for (int i = 0; i < 4; i++) {
        float4 v = r4[tid + i * 256];
        v.x = __expf(v.x - mx); v.y = __expf(v.y - mx);
        v.z = __expf(v.z - mx); v.w = __expf(v.w - mx);
        r4[tid + i * 256] = v;
        lsum += v.x + v.y + v.z + v.w;
    }
    red[tid] = lsum; __syncthreads();
    for (int s = 128; s > 0; s >>= 1) {
        if (tid < s) red[tid] += red[tid + s];
        __syncthreads();
    }
    const float inv = 1.0f / red[0];
#pragma unroll
    for (int i = 0; i < 4; i++) {
        float4 v = r4[tid + i * 256];
        v.x *= inv; v.y *= inv; v.z *= inv; v.w *= inv;
        p4[tid + i * 256] = v;
    }
}

// ---------------- k5: T[b] = softmax(K)[b] . x_b^T  ([64,256], K-dim m) ----------------
// grid (16 m-splits, B_), block 256, atomic-accumulated into g_T.
__global__ __launch_bounds__(256) void k5_T(const float* __restrict__ x) {
    __shared__ float sA[64][33];
    __shared__ float sB2[C_][33];
    const int ms = blockIdx.x, b = blockIdx.y, tid = threadIdx.x;
    const int ty = tid >> 5, tx = tid & 31;  // rows ty*8+i (8), cols tx+32*j (8)
    const float* Ab = g_P + (size_t)b * UK * M_ + ms * 256;
    const float* xb = x + (size_t)b * C_ * M_ + ms * 256;
    const int r0 = tid >> 5, mm0 = tid & 31;

    float acc[8][8];
#pragma unroll
    for (int i = 0; i < 8; i++)
#pragma unroll
        for (int j = 0; j < 8; j++) acc[i][j] = 0.f;

    for (int mc = 0; mc < 256; mc += 32) {
        __syncthreads();
#pragma unroll
        for (int i = 0; i < 8; i++) {
            int r = r0 + i * 8;
            sA[r][mm0] = Ab[(size_t)r * M_ + mc + mm0];
        }
#pragma unroll
        for (int i = 0; i < 32; i++) {
            int r = r0 + i * 8;
            sB2[r][mm0] = xb[(size_t)r * M_ + mc + mm0];
        }
        __syncthreads();
#pragma unroll
        for (int mm = 0; mm < 32; mm++) {
            float a[8], bb[8];
#pragma unroll
            for (int i = 0; i < 8; i++) a[i] = sA[ty * 8 + i][mm];
#pragma unroll
            for (int j = 0; j < 8; j++) bb[j] = sB2[tx + 32 * j][mm];
#pragma unroll
            for (int i = 0; i < 8; i++)
#pragma unroll
                for (int j = 0; j < 8; j++) acc[i][j] += a[i] * bb[j];
        }
    }
#pragma unroll
    for (int i = 0; i < 8; i++)
#pragma unroll
        for (int j = 0; j < 8; j++)
            atomicAdd(&g_T[((size_t)b * UK + ty * 8 + i) * C_ + tx + 32 * j], acc[i][j]);
}

// ---------------- k6: context[b,k,v] = sum_u T[b,u,k,:] . WvEff[u*256+v,:] ----------------
// grid (UD, B_), block 256 (thread = v), atomic-accumulated over u into g_ctx.
__global__ __launch_bounds__(256) void k6_ctx() {
    __shared__ float sT[16][C_];
    __shared__ float sW[VD][17];
    const int u = blockIdx.x, b = blockIdx.y, tid = threadIdx.x;
    const float* Tsrc = g_T + ((size_t)b * UK + u * 16) * C_;
#pragma unroll
    for (int i = 0; i < 16; i++) sT[i][tid] = Tsrc[i * C_ + tid];

    float acc[16];
#pragma unroll
    for (int i = 0; i < 16; i++) acc[i] = 0.f;
    const float* Wsrc = g_WvEff + (size_t)u * VD * C_;
    const int lr0 = tid >> 4, lc0 = tid & 15;

    for (int c0 = 0; c0 < C_; c0 += 16) {
        __syncthreads();
#pragma unroll
        for (int i = 0; i < 16; i++) {
            int r = lr0 + i * 16;
            sW[r][lc0] = Wsrc[r * C_ + c0 + lc0];
        }
        __syncthreads();
#pragma unroll
        for (int cc = 0; cc < 16; cc++) {
            float wv = sW[tid][cc];
#pragma unroll
            for (int kk = 0; kk < 16; kk++)
                acc[kk] += sT[kk][c0 + cc] * wv;
        }
    }
#pragma unroll
    for (int kk = 0; kk < 16; kk++)
        atomicAdd(&g_ctx[((size_t)b * KD + kk) * VD + tid], acc[kk]);
}

// ---------------- k7: y[b,v,m] = sum_k Q[b,k,m] * (ctx[b,k,v] + cb[v]) ----------------
// grid (16 m-tiles, B_), block 256 (thread = m within tile).
__global__ __launch_bounds__(256) void k7_y(float* __restrict__ y) {
    __shared__ float sctx[16][VD];
    __shared__ float sQ[16][257];
    const int mt = blockIdx.x, b = blockIdx.y, tid = threadIdx.x;
    const float cbv = g_cb[tid];
#pragma unroll
    for (int i = 0; i < 16; i++)
        sctx[i][tid] = g_ctx[((size_t)b * KD + i) * VD + tid] + cbv;
    const float* Qb = g_Q + (size_t)b * KD * M_ + mt * 256;
#pragma unroll
    for (int i = 0; i < 16; i++) sQ[i][tid] = Qb[(size_t)i * M_ + tid];
    __syncthreads();

    float q[16];
#pragma unroll
    for (int i = 0; i < 16; i++) q[i] = sQ[i][tid];
    float* yb = y + (size_t)b * VD * M_ + mt * 256 + tid;
    for (int v = 0; v < VD; v += 4) {
        float4 a = make_float4(0.f, 0.f, 0.f, 0.f);
#pragma unroll
        for (int kk = 0; kk < 16; kk++) {
            const float4 cv = *(const float4*)&sctx[kk][v];
            a.x += q[kk] * cv.x; a.y += q[kk] * cv.y;
            a.z += q[kk] * cv.z; a.w += q[kk] * cv.w;
        }
        yb[(size_t)(v + 0) * M_] = a.x;
        yb[(size_t)(v + 1) * M_] = a.y;
        yb[(size_t)(v + 2) * M_] = a.z;
        yb[(size_t)(v + 3) * M_] = a.w;
    }
}

// ---------------- launch ----------------
extern "C" void kernel_launch(void* const* d_in, const int* in_sizes, int n_in,
                              void* d_out, int out_size) {
    const float* x   = (const float*)d_in[0];
    const float* Wq  = (const float*)d_in[1];
    const float* bq  = (const float*)d_in[2];
    const float* Wk  = (const float*)d_in[3];
    const float* bk  = (const float*)d_in[4];
    const float* Wv  = (const float*)d_in[5];
    const float* bv  = (const float*)d_in[6];
    const float* gq  = (const float*)d_in[7];
    const float* btq = (const float*)d_in[8];
    const float* gv  = (const float*)d_in[9];
    const float* btv = (const float*)d_in[10];
    float* y = (float*)d_out;

    k0_zero<<<64, 256>>>();
    k1_gram<<<dim3(4, B_, 4), 256>>>(x);
    k2_params<<<69, 256>>>(Wq, bq, Wk, bk, Wv, bv, gq, btq, gv, btv);
    k3_qk<<<dim3(32, B_), 256>>>(x);
    k4_softmax<<<B_ * UK, 256>>>();
    k5_T<<<dim3(16, B_), 256>>>(x);
    k6_ctx<<<dim3(UD, B_), 256>>>();
    k7_y<<<dim3(16, B_), 256>>>(y);
}

// round 2
// speedup vs baseline: 1.4922x; 1.4922x over previous
#include <cuda_runtime.h>

#define B_  16
#define C_  256
#define M_  4096
#define NSf 65536.0f
#define KD  16
#define UD  4
#define UK  64
#define UV  1024
#define VD  256
#define EPSBN 1e-5f

// ---------------- scratch ----------------
__device__ float g_G[C_ * C_];
__device__ float g_s[C_];
__device__ float g_Wqk[80 * C_];
__device__ float g_bqk[80];
__device__ float g_WvEff[UV * C_];
__device__ float g_cb[VD];
__device__ float g_Q[B_ * KD * M_];
__device__ float g_P[B_ * UK * M_];
__device__ float g_T[B_ * UK * C_];
__device__ float g_ctx[B_ * KD * VD];

// ---------------- tf32 mma helpers ----------------
__device__ __forceinline__ unsigned f2tf(float f) {
    unsigned u; asm("cvt.rna.tf32.f32 %0, %1;" : "=r"(u) : "f"(f)); return u;
}
__device__ __forceinline__ void mma8(float c[4], const unsigned a[4], const unsigned b[2]) {
    asm volatile("mma.sync.aligned.m16n8k8.row.col.f32.tf32.tf32.f32 "
                 "{%0,%1,%2,%3}, {%4,%5,%6,%7}, {%8,%9}, {%0,%1,%2,%3};"
                 : "+f"(c[0]), "+f"(c[1]), "+f"(c[2]), "+f"(c[3])
                 : "r"(a[0]), "r"(a[1]), "r"(a[2]), "r"(a[3]), "r"(b[0]), "r"(b[1]));
}

// ---------------- k0: zero atomic-accumulated scratch ----------------
__global__ void k0_zero() {
    int i = blockIdx.x * blockDim.x + threadIdx.x;
    int n = blockDim.x * gridDim.x;
    for (int j = i; j < C_ * C_; j += n) g_G[j] = 0.f;
    for (int j = i; j < C_; j += n) { g_s[j] = 0.f; g_cb[j] = 0.f; }
    for (int j = i; j < B_ * UK * C_; j += n) g_T[j] = 0.f;
    for (int j = i; j < B_ * KD * VD; j += n) g_ctx[j] = 0.f;
}

// ---------------- k1: Gram G = X X^T (tf32 mma) + column sums ----------------
// grid (4 tiles of 128x128, B_, 8 k-chunks of 512), block 256 (8 warps, 2x4).
__global__ __launch_bounds__(256) void k1_gram(const float* __restrict__ x) {
    __shared__ __align__(16) unsigned As[4 * 8 * 32 * 4];   // 128x32, A-fragment order
    __shared__ __align__(16) unsigned Bs[4 * 16 * 32 * 2];  // 128x32, B-fragment order
    const int tile = blockIdx.x, b = blockIdx.y, ks = blockIdx.z;
    const int ti = tile >> 1, tj = tile & 1;
    const int tid = threadIdx.x, lane = tid & 31, warp = tid >> 5;
    const int wm = warp >> 2, wn = warp & 3;
    const float* Asrc = x + (size_t)b * C_ * M_ + (size_t)ti * 128 * M_ + ks * 512;
    const float* Bsrc = x + (size_t)b * C_ * M_ + (size_t)tj * 128 * M_ + ks * 512;
    const bool diag = (ti == tj);

    float acc[4][4][4];
#pragma unroll
    for (int i = 0; i < 4; i++)
#pragma unroll
        for (int j = 0; j < 4; j++)
#pragma unroll
            for (int r = 0; r < 4; r++) acc[i][j][r] = 0.f;
    float rsum[4] = {0.f, 0.f, 0.f, 0.f};

    for (int kc = 0; kc < 512; kc += 32) {
        __syncthreads();
        // stage A slab (128 rows x 32 k), fragment order, tf32-converted
#pragma unroll
        for (int it = 0; it < 4; it++) {
            int e = tid + it * 256;
            int row = e >> 3, kq = e & 7;
            float4 v = *(const float4*)(Asrc + (size_t)row * M_ + kc + kq * 4);
            if (diag) rsum[it] += v.x + v.y + v.z + v.w;
            int base = (((kq >> 1) * 8 + (row >> 4)) * 32 + (row & 7) * 4) * 4
                       + ((row >> 3) & 1) + 2 * (kq & 1);
            As[base + 0]  = f2tf(v.x);
            As[base + 4]  = f2tf(v.y);
            As[base + 8]  = f2tf(v.z);
            As[base + 12] = f2tf(v.w);
        }
        // stage B slab (128 rows x 32 k)
#pragma unroll
        for (int it = 0; it < 4; it++) {
            int e = tid + it * 256;
            int row = e >> 3, kq = e & 7;
            float4 v = *(const float4*)(Bsrc + (size_t)row * M_ + kc + kq * 4);
            int base = (((kq >> 1) * 16 + (row >> 3)) * 32 + (row & 7) * 4) * 2 + (kq & 1);
            Bs[base + 0] = f2tf(v.x);
            Bs[base + 2] = f2tf(v.y);
            Bs[base + 4] = f2tf(v.z);
            Bs[base + 6] = f2tf(v.w);
        }
        __syncthreads();
#pragma unroll
        for (int kb = 0; kb < 4; kb++) {
            unsigned a[4][4], bb[4][2];
#pragma unroll
            for (int mf = 0; mf < 4; mf++)
                *(uint4*)a[mf] = *(const uint4*)&As[((kb * 8 + wm * 4 + mf) * 32 + lane) * 4];
#pragma unroll
            for (int nf = 0; nf < 4; nf++)
                *(uint2*)bb[nf] = *(const uint2*)&Bs[((kb * 16 + wn * 4 + nf) * 32 + lane) * 2];
#pragma unroll
            for (int mf = 0; mf < 4; mf++)
#pragma unroll
                for (int nf = 0; nf < 4; nf++) mma8(acc[mf][nf], a[mf], bb[nf]);
        }
    }
    const int g = lane >> 2, t = lane & 3;
#pragma unroll
    for (int mf = 0; mf < 4; mf++) {
        int row = ti * 128 + wm * 64 + mf * 16 + g;
#pragma unroll
        for (int nf = 0; nf < 4; nf++) {
            int col = tj * 128 + wn * 32 + nf * 8 + 2 * t;
            atomicAdd(&g_G[row * C_ + col],           acc[mf][nf][0]);
            atomicAdd(&g_G[row * C_ + col + 1],       acc[mf][nf][1]);
            atomicAdd(&g_G[(row + 8) * C_ + col],     acc[mf][nf][2]);
            atomicAdd(&g_G[(row + 8) * C_ + col + 1], acc[mf][nf][3]);
        }
    }
    if (diag) {
#pragma unroll
        for (int it = 0; it < 4; it++) {
            float v = rsum[it];
            v += __shfl_down_sync(0xffffffffu, v, 4, 8);
            v += __shfl_down_sync(0xffffffffu, v, 2, 8);
            v += __shfl_down_sync(0xffffffffu, v, 1, 8);
            if ((tid & 7) == 0) atomicAdd(&g_s[ti * 128 + (tid >> 3) + it * 32], v);
        }
    }
}

// ---------------- k2: BN folding + Wk copy (unchanged) ----------------
__global__ __launch_bounds__(256) void k2_params(
    const float* __restrict__ Wq, const float* __restrict__ bq,
    const float* __restrict__ Wk, const float* __restrict__ bk,
    const float* __restrict__ Wv, const float* __restrict__ bv,
    const float* __restrict__ gq, const float* __restrict__ btq,
    const float* __restrict__ gv, const float* __restrict__ btv) {
    const int blk = blockIdx.x, tid = threadIdx.x;

    if (blk >= 65) {
        int base = (blk - 65) * 16;
#pragma unroll
        for (int i = 0; i < 16; i++)
            g_Wqk[(16 + base + i) * C_ + tid] = Wk[(base + i) * C_ + tid];
        if (tid < 16) g_bqk[16 + base + tid] = bk[base + tid];
        return;
    }

    __shared__ float w[16][C_];
    __shared__ float qf[16], ds[16], alph[16];
    const bool isQ = (blk == 0);
    const float* Wsrc = isQ ? Wq : (Wv + (size_t)(blk - 1) * 16 * C_);
#pragma unroll
    for (int i = 0; i < 16; i++) w[i][tid] = Wsrc[i * C_ + tid];
    if (tid < 16) { qf[tid] = 0.f; ds[tid] = 0.f; }
    __syncthreads();

    float inner[16];
#pragma unroll
    for (int ch = 0; ch < 16; ch++) inner[ch] = 0.f;
    const int c = tid;
    for (int r = 0; r < C_; r++) {
        float grc = g_G[r * C_ + c];
#pragma unroll
        for (int ch = 0; ch < 16; ch++) inner[ch] += w[ch][r] * grc;
    }
    const float sc = g_s[c];
    const int lane = tid & 31;
#pragma unroll
    for (int ch = 0; ch < 16; ch++) {
        float vq = inner[ch] * w[ch][c];
        float vd = w[ch][c] * sc;
#pragma unroll
        for (int o = 16; o > 0; o >>= 1) {
            vq += __shfl_down_sync(0xffffffffu, vq, o);
            vd += __shfl_down_sync(0xffffffffu, vd, o);
        }
        if (lane == 0) { atomicAdd(&qf[ch], vq); atomicAdd(&ds[ch], vd); }
    }
    __syncthreads();

    if (tid < 16) {
        int ch = tid;
        float bias, gamma, beta;
        if (isQ) { bias = bq[ch]; gamma = gq[ch]; beta = btq[ch]; }
        else {
            int gch = (blk - 1) * 16 + ch;
            bias = bv[gch]; gamma = gv[gch]; beta = btv[gch];
        }
        float dsv  = ds[ch];
        float mean = dsv / NSf + bias;
        float e2   = (qf[ch] + 2.f * bias * dsv) / NSf + bias * bias;
        float var  = e2 - mean * mean;
        float a    = gamma * rsqrtf(var + EPSBN);
        alph[ch]   = a;
        float be   = beta + a * (bias - mean);
        if (isQ) g_bqk[ch] = be;
        else {
            int gch = (blk - 1) * 16 + ch;
            atomicAdd(&g_cb[gch & (VD - 1)], be);
        }
    }
    __syncthreads();
#pragma unroll
    for (int i = 0; i < 16; i++) {
        float val = alph[i] * w[i][tid];
        if (isQ) g_Wqk[i * C_ + tid] = val;
        else     g_WvEff[((size_t)(blk - 1) * 16 + i) * C_ + tid] = val;
    }
}

// ---------------- k3: fused Q+K GEMM (tf32 mma) ----------------
// out[80, 4096] per b. grid (32 n-tiles of 128, B_), block 256 (8 warps, n-slice 16 each).
__global__ __launch_bounds__(256) void k3_qk(const float* __restrict__ x) {
    __shared__ __align__(16) unsigned As[4 * 5 * 32 * 4];   // 80x32
    __shared__ __align__(16) unsigned Bs[4 * 16 * 32 * 2];  // 128n x 32k
    const int mt = blockIdx.x, b = blockIdx.y;
    const int tid = threadIdx.x, lane = tid & 31, warp = tid >> 5;
    const float* Bx = x + (size_t)b * C_ * M_ + mt * 128;

    float acc[5][2][4];
#pragma unroll
    for (int i = 0; i < 5; i++)
#pragma unroll
        for (int j = 0; j < 2; j++)
#pragma unroll
            for (int r = 0; r < 4; r++) acc[i][j][r] = 0.f;

    for (int kc = 0; kc < C_; kc += 32) {
        __syncthreads();
        // stage A: Wqk[80][kc..kc+32]
        for (int e = tid; e < 640; e += 256) {
            int row = e >> 3, kq = e & 7;
            float4 v = *(const float4*)(g_Wqk + row * C_ + kc + kq * 4);
            int base = (((kq >> 1) * 5 + (row >> 4)) * 32 + (row & 7) * 4) * 4
                       + ((row >> 3) & 1) + 2 * (kq & 1);
            As[base + 0]  = f2tf(v.x);
            As[base + 4]  = f2tf(v.y);
            As[base + 8]  = f2tf(v.z);
            As[base + 12] = f2tf(v.w);
        }
        // stage B: x[kc+kk][mt*128 + n]  (n-contiguous source)
#pragma unroll
        for (int it = 0; it < 4; it++) {
            int e = tid + it * 256;
            int kk = e >> 5, nq = e & 31;
            float4 v = *(const float4*)(Bx + (size_t)(kc + kk) * M_ + nq * 4);
            int base = (((kk >> 3) * 16 + (nq >> 1)) * 32 + ((nq & 1) << 4) + (kk & 3)) * 2
                       + ((kk >> 2) & 1);
            Bs[base + 0]  = f2tf(v.x);
            Bs[base + 8]  = f2tf(v.y);
            Bs[base + 16] = f2tf(v.z);
            Bs[base + 24] = f2tf(v.w);
        }
        __syncthreads();
#pragma unroll
        for (int kb = 0; kb < 4; kb++) {
            unsigned a[5][4], bb[2][2];
#pragma unroll
            for (int mf = 0; mf < 5; mf++)
                *(uint4*)a[mf] = *(const uint4*)&As[((kb * 5 + mf) * 32 + lane) * 4];
#pragma unroll
            for (int nf = 0; nf < 2; nf++)
                *(uint2*)bb[nf] = *(const uint2*)&Bs[((kb * 16 + warp * 2 + nf) * 32 + lane) * 2];
#pragma unroll
            for (int mf = 0; mf < 5; mf++)
#pragma unroll
                for (int nf = 0; nf < 2; nf++) mma8(acc[mf][nf], a[mf], bb[nf]);
        }
    }
    const int g = lane >> 2, t = lane & 3;
#pragma unroll
    for (int mf = 0; mf < 5; mf++) {
#pragma unroll
        for (int nf = 0; nf < 2; nf++) {
            int col = mt * 128 + warp * 16 + nf * 8 + 2 * t;
#pragma unroll
            for (int h = 0; h < 2; h++) {
                int row = mf * 16 + g + h * 8;
                float bias = g_bqk[row];
                float2 v = make_float2(acc[mf][nf][h * 2 + 0] + bias,
                                       acc[mf][nf][h * 2 + 1] + bias);
                float* dst = (row < 16) ? &g_Q[((size_t)b * KD + row) * M_ + col]
                                        : &g_P[((size_t)b * UK + row - 16) * M_ + col];
                *(float2*)dst = v;
            }
        }
    }
}

// ---------------- k4: row softmax of K (unchanged) ----------------
__global__ __launch_bounds__(256) void k4_softmax() {
    __shared__ float row[M_];
    __shared__ float red[256];
    const int rid = blockIdx.x, tid = threadIdx.x;
    float* p = g_P + (size_t)rid * M_;
    float4* p4 = (float4*)p;
    float4* r4 = (float4*)row;

    float lmax = -3.0e38f;
#pragma unroll
    for (int i = 0; i < 4; i++) {
        float4 v = p4[tid + i * 256];
        r4[tid + i * 256] = v;
        lmax = fmaxf(lmax, fmaxf(fmaxf(v.x, v.y), fmaxf(v.z, v.w)));
    }
    red[tid] = lmax; __syncthreads();
    for (int s = 128; s > 0; s >>= 1) {
        if (tid < s) red[tid] = fmaxf(red[tid], red[tid + s]);
        __syncthreads();
    }
    const float mx = red[0];
    __syncthreads();

    float lsum = 0.f;
#pragma unroll
    for (int i = 0; i < 4; i++) {
        float4 v = r4[tid + i * 256];
        v.x = __expf(v.x - mx); v.y = __expf(v.y - mx);
        v.z = __expf(v.z - mx); v.w = __expf(v.w - mx);
        r4[tid + i * 256] = v;
        lsum += v.x + v.y + v.z + v.w;
    }
    red[tid] = lsum; __syncthreads();
    for (int s = 128; s > 0; s >>= 1) {
        if (tid < s) red[tid] += red[tid + s];
        __syncthreads();
    }
    const float inv = 1.0f / red[0];
#pragma unroll
    for (int i = 0; i < 4; i++) {
        float4 v = r4[tid + i * 256];
        v.x *= inv; v.y *= inv; v.z *= inv; v.w *= inv;
        p4[tid + i * 256] = v;
    }
}

// ---------------- k5: T[b] = softmax(K)[b] . x_b^T  (tf32 mma) ----------------
// grid (16 k-splits of 256, B_), block 256 (8 warps 2x4), atomicAdd into g_T.
__global__ __launch_bounds__(256) void k5_T(const float* __restrict__ x) {
    __shared__ __align__(16) unsigned As[4 * 4 * 32 * 4];   // 64x32
    __shared__ __align__(16) unsigned Bs[4 * 32 * 32 * 2];  // 256x32
    const int ks = blockIdx.x, b = blockIdx.y;
    const int tid = threadIdx.x, lane = tid & 31, warp = tid >> 5;
    const int wm = warp >> 2, wn = warp & 3;
    const float* Ap = g_P + (size_t)b * UK * M_ + ks * 256;
    const float* Bx = x + (size_t)b * C_ * M_ + ks * 256;

    float acc[2][8][4];
#pragma unroll
    for (int i = 0; i < 2; i++)
#pragma unroll
        for (int j = 0; j < 8; j++)
#pragma unroll
            for (int r = 0; r < 4; r++) acc[i][j][r] = 0.f;

    for (int kc = 0; kc < 256; kc += 32) {
        __syncthreads();
        // stage A: P slab 64 rows x 32 k
#pragma unroll
        for (int it = 0; it < 2; it++) {
            int e = tid + it * 256;
            int row = e >> 3, kq = e & 7;
            float4 v = *(const float4*)(Ap + (size_t)row * M_ + kc + kq * 4);
            int base = (((kq >> 1) * 4 + (row >> 4)) * 32 + (row & 7) * 4) * 4
                       + ((row >> 3) & 1) + 2 * (kq & 1);
            As[base + 0]  = f2tf(v.x);
            As[base + 4]  = f2tf(v.y);
            As[base + 8]  = f2tf(v.z);
            As[base + 12] = f2tf(v.w);
        }
        // stage B: x slab 256 rows x 32 k
#pragma unroll
        for (int it = 0; it < 8; it++) {
            int e = tid + it * 256;
            int row = e >> 3, kq = e & 7;
            float4 v = *(const float4*)(Bx + (size_t)row * M_ + kc + kq * 4);
            int base = (((kq >> 1) * 32 + (row >> 3)) * 32 + (row & 7) * 4) * 2 + (kq & 1);
            Bs[base + 0] = f2tf(v.x);
            Bs[base + 2] = f2tf(v.y);
            Bs[base + 4] = f2tf(v.z);
            Bs[base + 6] = f2tf(v.w);
        }
        __syncthreads();
#pragma unroll
        for (int kb = 0; kb < 4; kb++) {
            unsigned a[2][4], bb[8][2];
#pragma unroll
            for (int mf = 0; mf < 2; mf++)
                *(uint4*)a[mf] = *(const uint4*)&As[((kb * 4 + wm * 2 + mf) * 32 + lane) * 4];
#pragma unroll
            for (int nf = 0; nf < 8; nf++)
                *(uint2*)bb[nf] = *(const uint2*)&Bs[((kb * 32 + wn * 8 + nf) * 32 + lane) * 2];
#pragma unroll
            for (int mf = 0; mf < 2; mf++)
#pragma unroll
                for (int nf = 0; nf < 8; nf++) mma8(acc[mf][nf], a[mf], bb[nf]);
        }
    }
    const int g = lane >> 2, t = lane & 3;
#pragma unroll
    for (int mf = 0; mf < 2; mf++) {
        int row = wm * 32 + mf * 16 + g;
#pragma unroll
        for (int nf = 0; nf < 8; nf++) {
            int col = wn * 64 + nf * 8 + 2 * t;
            atomicAdd(&g_T[((size_t)b * UK + row) * C_ + col],           acc[mf][nf][0]);
            atomicAdd(&g_T[((size_t)b * UK + row) * C_ + col + 1],       acc[mf][nf][1]);
            atomicAdd(&g_T[((size_t)b * UK + row + 8) * C_ + col],       acc[mf][nf][2]);
            atomicAdd(&g_T[((size_t)b * UK + row + 8) * C_ + col + 1],   acc[mf][nf][3]);
        }
    }
}

// ---------------- k6: context (unchanged) ----------------
__global__ __launch_bounds__(256) void k6_ctx() {
    __shared__ float sT[16][C_];
    __shared__ float sW[VD][17];
    const int u = blockIdx.x, b = blockIdx.y, tid = threadIdx.x;
    const float* Tsrc = g_T + ((size_t)b * UK + u * 16) * C_;
#pragma unroll
    for (int i = 0; i < 16; i++) sT[i][tid] = Tsrc[i * C_ + tid];

    float acc[16];
#pragma unroll
    for (int i = 0; i < 16; i++) acc[i] = 0.f;
    const float* Wsrc = g_WvEff + (size_t)u * VD * C_;
    const int lr0 = tid >> 4, lc0 = tid & 15;

    for (int c0 = 0; c0 < C_; c0 += 16) {
        __syncthreads();
#pragma unroll
        for (int i = 0; i < 16; i++) {
            int r = lr0 + i * 16;
            sW[r][lc0] = Wsrc[r * C_ + c0 + lc0];
        }
        __syncthreads();
#pragma unroll
        for (int cc = 0; cc < 16; cc++) {
            float wv = sW[tid][cc];
#pragma unroll
            for (int kk = 0; kk < 16; kk++)
                acc[kk] += sT[kk][c0 + cc] * wv;
        }
    }
#pragma unroll
    for (int kk = 0; kk < 16; kk++)
        atomicAdd(&g_ctx[((size_t)b * KD + kk) * VD + tid], acc[kk]);
}

// ---------------- k7: y = Q^T ctx (unchanged) ----------------
__global__ __launch_bounds__(256) void k7_y(float* __restrict__ y) {
    __shared__ float sctx[16][VD];
    __shared__ float sQ[16][257];
    const int mt = blockIdx.x, b = blockIdx.y, tid = threadIdx.x;
    const float cbv = g_cb[tid];
#pragma unroll
    for (int i = 0; i < 16; i++)
        sctx[i][tid] = g_ctx[((size_t)b * KD + i) * VD + tid] + cbv;
    const float* Qb = g_Q + (size_t)b * KD * M_ + mt * 256;
#pragma unroll
    for (int i = 0; i < 16; i++) sQ[i][tid] = Qb[(size_t)i * M_ + tid];
    __syncthreads();

    float q[16];
#pragma unroll
    for (int i = 0; i < 16; i++) q[i] = sQ[i][tid];
    float* yb = y + (size_t)b * VD * M_ + mt * 256 + tid;
    for (int v = 0; v < VD; v += 4) {
        float4 a = make_float4(0.f, 0.f, 0.f, 0.f);
#pragma unroll
        for (int kk = 0; kk < 16; kk++) {
            const float4 cv = *(const float4*)&sctx[kk][v];
            a.x += q[kk] * cv.x; a.y += q[kk] * cv.y;
            a.z += q[kk] * cv.z; a.w += q[kk] * cv.w;
        }
        yb[(size_t)(v + 0) * M_] = a.x;
        yb[(size_t)(v + 1) * M_] = a.y;
        yb[(size_t)(v + 2) * M_] = a.z;
        yb[(size_t)(v + 3) * M_] = a.w;
    }
}

// ---------------- launch ----------------
extern "C" void kernel_launch(void* const* d_in, const int* in_sizes, int n_in,
                              void* d_out, int out_size) {
    const float* x   = (const float*)d_in[0];
    const float* Wq  = (const float*)d_in[1];
    const float* bq  = (const float*)d_in[2];
    const float* Wk  = (const float*)d_in[3];
    const float* bk  = (const float*)d_in[4];
    const float* Wv  = (const float*)d_in[5];
    const float* bv  = (const float*)d_in[6];
    const float* gq  = (const float*)d_in[7];
    const float* btq = (const float*)d_in[8];
    const float* gv  = (const float*)d_in[9];
    const float* btv = (const float*)d_in[10];
    float* y = (float*)d_out;

    k0_zero<<<64, 256>>>();
    k1_gram<<<dim3(4, B_, 8), 256>>>(x);
    k2_params<<<69, 256>>>(Wq, bq, Wk, bk, Wv, bv, gq, btq, gv, btv);
    k3_qk<<<dim3(32, B_), 256>>>(x);
    k4_softmax<<<B_ * UK, 256>>>();
    k5_T<<<dim3(16, B_), 256>>>(x);
    k6_ctx<<<dim3(UD, B_), 256>>>();
    k7_y<<<dim3(16, B_), 256>>>(y);
}

// round 3
// speedup vs baseline: 2.3374x; 1.5664x over previous
#include <cuda_runtime.h>
#include <cstdint>

#define B_  16
#define C_  256
#define M_  4096
#define NSf 65536.0f
#define KD  16
#define UD  4
#define UK  64
#define UV  1024
#define VD  256
#define EPSBN 1e-5f

// ---------------- scratch ----------------
__device__ float g_G[C_ * C_];
__device__ float g_s[C_];
__device__ float g_Wqk[80 * C_];
__device__ float g_bqk[80];
__device__ float g_WvEff[UV * C_];
__device__ float g_cb[VD];
__device__ float g_Q[B_ * KD * M_];
__device__ float g_P[B_ * UK * M_];
__device__ float g_T[B_ * UK * C_];
__device__ float g_ctx[B_ * KD * VD];

// ---------------- helpers ----------------
__device__ __forceinline__ unsigned f2tf(float f) {
    unsigned u; asm("cvt.rna.tf32.f32 %0, %1;" : "=r"(u) : "f"(f)); return u;
}
__device__ __forceinline__ void mma8(float c[4], const unsigned a[4], const unsigned b[2]) {
    asm volatile("mma.sync.aligned.m16n8k8.row.col.f32.tf32.tf32.f32 "
                 "{%0,%1,%2,%3}, {%4,%5,%6,%7}, {%8,%9}, {%0,%1,%2,%3};"
                 : "+f"(c[0]), "+f"(c[1]), "+f"(c[2]), "+f"(c[3])
                 : "r"(a[0]), "r"(a[1]), "r"(a[2]), "r"(a[3]), "r"(b[0]), "r"(b[1]));
}
__device__ __forceinline__ unsigned sptr(const void* p) {
    return (unsigned)__cvta_generic_to_shared(p);
}
__device__ __forceinline__ void ldsm4(unsigned d[4], unsigned addr) {
    asm volatile("ldmatrix.sync.aligned.m8n8.x4.shared.b16 {%0,%1,%2,%3}, [%4];"
                 : "=r"(d[0]), "=r"(d[1]), "=r"(d[2]), "=r"(d[3]) : "r"(addr));
}
__device__ __forceinline__ void cpa16(unsigned saddr, const void* g) {
    asm volatile("cp.async.cg.shared.global [%0], [%1], 16;" :: "r"(saddr), "l"(g));
}
__device__ __forceinline__ void cpcommit() { asm volatile("cp.async.commit_group;"); }
__device__ __forceinline__ void cpwait1() { asm volatile("cp.async.wait_group 1;"); }

// A-fragment ldmatrix address (16-row group at R0, k-block kb), 128B rows, swizzled
__device__ __forceinline__ unsigned a_addr(unsigned base, int R0, int kb, int lane) {
    int row = R0 + (((lane >> 3) & 1) << 3) + (lane & 7);
    int ch  = kb * 2 + (lane >> 4);
    return base + row * 128 + ((ch ^ (row & 7)) << 4);
}
// B-fragment ldmatrix address (16-n group at N0, k-block kb)
__device__ __forceinline__ unsigned b_addr(unsigned base, int N0, int kb, int lane) {
    int row = N0 + ((lane >> 4) << 3) + (lane & 7);
    int ch  = kb * 2 + ((lane >> 3) & 1);
    return base + row * 128 + ((ch ^ (row & 7)) << 4);
}

// ---------------- k0: zero scratch ----------------
__global__ void k0_zero() {
    int i = blockIdx.x * blockDim.x + threadIdx.x;
    int n = blockDim.x * gridDim.x;
    for (int j = i; j < C_ * C_; j += n) g_G[j] = 0.f;
    for (int j = i; j < C_; j += n) { g_s[j] = 0.f; g_cb[j] = 0.f; }
    for (int j = i; j < B_ * UK * C_; j += n) g_T[j] = 0.f;
    for (int j = i; j < B_ * KD * VD; j += n) g_ctx[j] = 0.f;
}

// ---------------- k1: Gram G = X X^T (tf32 mma, ldmatrix, cp.async pipeline) ----
// grid (3 sym tiles, B_, 4 k-splits of 1024), block 256 (8 warps 2x4).
// smem: 3 stages x (A 128x32f + B 128x32f) = 3 x 32KB.
__global__ __launch_bounds__(256, 2) void k1_gram(const float* __restrict__ x) {
    extern __shared__ float smem[];
    const int t3 = blockIdx.x;
    const int ti = (t3 == 1) ? 1 : 0, tj = (t3 == 0) ? 0 : 1;
    const int b = blockIdx.y, kz = blockIdx.z;
    const int tid = threadIdx.x, lane = tid & 31, warp = tid >> 5;
    const int wm = warp >> 2, wn = warp & 3;
    const bool diag = (ti == tj);
    const float* Ag = x + (size_t)b * C_ * M_ + (size_t)(ti * 128) * M_ + kz * 1024;
    const float* Bg = x + (size_t)b * C_ * M_ + (size_t)(tj * 128) * M_ + kz * 1024;
    const unsigned s0 = sptr(smem);
    const int NC = 32;

    float acc[4][4][4];
#pragma unroll
    for (int i = 0; i < 4; i++)
#pragma unroll
        for (int j = 0; j < 4; j++)
#pragma unroll
            for (int r = 0; r < 4; r++) acc[i][j][r] = 0.f;
    float rsum[4] = {0.f, 0.f, 0.f, 0.f};

    auto stage = [&](int c, int s) {
        const float* As = Ag + c * 32;
        const float* Bs = Bg + c * 32;
        unsigned ab = s0 + s * 32768u;
        unsigned bb = ab + 16384u;
#pragma unroll
        for (int it = 0; it < 4; it++) {
            int id = tid + it * 256;
            int r = id >> 3, ch = id & 7;
            unsigned sw = (unsigned)(r * 128 + ((ch ^ (r & 7)) << 4));
            cpa16(ab + sw, As + (size_t)r * M_ + ch * 4);
            cpa16(bb + sw, Bs + (size_t)r * M_ + ch * 4);
        }
    };

    stage(0, 0); cpcommit();
    stage(1, 1); cpcommit();

    for (int i = 0; i < NC; i++) {
        cpwait1(); __syncthreads();
        int s = i % 3;
        unsigned ab = s0 + s * 32768u, bb = ab + 16384u;
#pragma unroll
        for (int kb = 0; kb < 4; kb++) {
            unsigned af[4][4], bf[2][4];
#pragma unroll
            for (int mf = 0; mf < 4; mf++)
                ldsm4(af[mf], a_addr(ab, wm * 64 + mf * 16, kb, lane));
#pragma unroll
            for (int p = 0; p < 2; p++) {
                ldsm4(bf[p], b_addr(bb, wn * 32 + p * 16, kb, lane));
                if (diag && wm == 0) {
                    rsum[p * 2 + 0] += __uint_as_float(bf[p][0]) + __uint_as_float(bf[p][1]);
                    rsum[p * 2 + 1] += __uint_as_float(bf[p][2]) + __uint_as_float(bf[p][3]);
                }
            }
#pragma unroll
            for (int mf = 0; mf < 4; mf++)
#pragma unroll
                for (int w = 0; w < 4; w++) af[mf][w] = f2tf(__uint_as_float(af[mf][w]));
#pragma unroll
            for (int p = 0; p < 2; p++)
#pragma unroll
                for (int w = 0; w < 4; w++) bf[p][w] = f2tf(__uint_as_float(bf[p][w]));
#pragma unroll
            for (int mf = 0; mf < 4; mf++)
#pragma unroll
                for (int p = 0; p < 2; p++) {
                    mma8(acc[mf][p * 2 + 0], af[mf], &bf[p][0]);
                    mma8(acc[mf][p * 2 + 1], af[mf], &bf[p][2]);
                }
        }
        if (i + 2 < NC) stage(i + 2, (i + 2) % 3);
        cpcommit();
    }

    const int g = lane >> 2, t = lane & 3;
#pragma unroll
    for (int mf = 0; mf < 4; mf++) {
        int row = ti * 128 + wm * 64 + mf * 16 + g;
#pragma unroll
        for (int nf = 0; nf < 4; nf++) {
            int col = tj * 128 + wn * 32 + nf * 8 + 2 * t;
            atomicAdd(&g_G[row * C_ + col],           acc[mf][nf][0]);
            atomicAdd(&g_G[row * C_ + col + 1],       acc[mf][nf][1]);
            atomicAdd(&g_G[(row + 8) * C_ + col],     acc[mf][nf][2]);
            atomicAdd(&g_G[(row + 8) * C_ + col + 1], acc[mf][nf][3]);
            if (!diag) {
                atomicAdd(&g_G[col * C_ + row],           acc[mf][nf][0]);
                atomicAdd(&g_G[(col + 1) * C_ + row],     acc[mf][nf][1]);
                atomicAdd(&g_G[col * C_ + row + 8],       acc[mf][nf][2]);
                atomicAdd(&g_G[(col + 1) * C_ + row + 8], acc[mf][nf][3]);
            }
        }
    }
    if (diag && wm == 0) {
#pragma unroll
        for (int sl = 0; sl < 4; sl++) {
            float v = rsum[sl];
            v += __shfl_down_sync(0xffffffffu, v, 2, 4);
            v += __shfl_down_sync(0xffffffffu, v, 1, 4);
            if ((lane & 3) == 0) {
                int n = tj * 128 + wn * 32 + (sl >> 1) * 16 + (sl & 1) * 8 + (lane >> 2);
                atomicAdd(&g_s[n], v);
            }
        }
    }
}

// ---------------- k2: BN folding + Wk copy (unchanged) ----------------
__global__ __launch_bounds__(256) void k2_params(
    const float* __restrict__ Wq, const float* __restrict__ bq,
    const float* __restrict__ Wk, const float* __restrict__ bk,
    const float* __restrict__ Wv, const float* __restrict__ bv,
    const float* __restrict__ gq, const float* __restrict__ btq,
    const float* __restrict__ gv, const float* __restrict__ btv) {
    const int blk = blockIdx.x, tid = threadIdx.x;

    if (blk >= 65) {
        int base = (blk - 65) * 16;
#pragma unroll
        for (int i = 0; i < 16; i++)
            g_Wqk[(16 + base + i) * C_ + tid] = Wk[(base + i) * C_ + tid];
        if (tid < 16) g_bqk[16 + base + tid] = bk[base + tid];
        return;
    }

    __shared__ float w[16][C_];
    __shared__ float qf[16], ds[16], alph[16];
    const bool isQ = (blk == 0);
    const float* Wsrc = isQ ? Wq : (Wv + (size_t)(blk - 1) * 16 * C_);
#pragma unroll
    for (int i = 0; i < 16; i++) w[i][tid] = Wsrc[i * C_ + tid];
    if (tid < 16) { qf[tid] = 0.f; ds[tid] = 0.f; }
    __syncthreads();

    float inner[16];
#pragma unroll
    for (int ch = 0; ch < 16; ch++) inner[ch] = 0.f;
    const int c = tid;
    for (int r = 0; r < C_; r++) {
        float grc = g_G[r * C_ + c];
#pragma unroll
        for (int ch = 0; ch < 16; ch++) inner[ch] += w[ch][r] * grc;
    }
    const float sc = g_s[c];
    const int lane = tid & 31;
#pragma unroll
    for (int ch = 0; ch < 16; ch++) {
        float vq = inner[ch] * w[ch][c];
        float vd = w[ch][c] * sc;
#pragma unroll
        for (int o = 16; o > 0; o >>= 1) {
            vq += __shfl_down_sync(0xffffffffu, vq, o);
            vd += __shfl_down_sync(0xffffffffu, vd, o);
        }
        if (lane == 0) { atomicAdd(&qf[ch], vq); atomicAdd(&ds[ch], vd); }
    }
    __syncthreads();

    if (tid < 16) {
        int ch = tid;
        float bias, gamma, beta;
        if (isQ) { bias = bq[ch]; gamma = gq[ch]; beta = btq[ch]; }
        else {
            int gch = (blk - 1) * 16 + ch;
            bias = bv[gch]; gamma = gv[gch]; beta = btv[gch];
        }
        float dsv  = ds[ch];
        float mean = dsv / NSf + bias;
        float e2   = (qf[ch] + 2.f * bias * dsv) / NSf + bias * bias;
        float var  = e2 - mean * mean;
        float a    = gamma * rsqrtf(var + EPSBN);
        alph[ch]   = a;
        float be   = beta + a * (bias - mean);
        if (isQ) g_bqk[ch] = be;
        else {
            int gch = (blk - 1) * 16 + ch;
            atomicAdd(&g_cb[gch & (VD - 1)], be);
        }
    }
    __syncthreads();
#pragma unroll
    for (int i = 0; i < 16; i++) {
        float val = alph[i] * w[i][tid];
        if (isQ) g_Wqk[i * C_ + tid] = val;
        else     g_WvEff[((size_t)(blk - 1) * 16 + i) * C_ + tid] = val;
    }
}

// ---------------- k3: fused Q+K GEMM (tf32 mma, ldmatrix) ----------------
// out[80, 4096] per b. grid (32 px-tiles of 128, B_), block 256.
// smem: 3 stages x (A 80x32f=10240B + B 128x32f=16384B) = 3 x 26624B.
__global__ __launch_bounds__(256, 2) void k3_qk(const float* __restrict__ x) {
    extern __shared__ float smem[];
    const int mt = blockIdx.x, b = blockIdx.y;
    const int tid = threadIdx.x, lane = tid & 31, warp = tid >> 5;
    const unsigned s0 = sptr(smem);
    const int NC = 8;
    const int p = tid & 127, q0 = tid >> 7;

    float acc[5][2][4];
#pragma unroll
    for (int i = 0; i < 5; i++)
#pragma unroll
        for (int j = 0; j < 2; j++)
#pragma unroll
            for (int r = 0; r < 4; r++) acc[i][j][r] = 0.f;

    auto stage = [&](int c, int s) {
        unsigned ab = s0 + s * 26624u;
        // A: Wqk 80 rows x 8 chunks via cp.async
#pragma unroll
        for (int it = 0; it < 3; it++) {
            int id = tid + it * 256;
            if (id < 640) {
                int r = id >> 3, ch = id & 7;
                cpa16(ab + r * 128 + ((ch ^ (r & 7)) << 4),
                      g_Wqk + r * C_ + c * 32 + ch * 4);
            }
        }
        // B: transpose-stage x -> [pixel][channel]
        const float* xc = x + (size_t)b * C_ * M_ + (size_t)(c * 32) * M_ + mt * 128;
        char* bbuf = (char*)smem + s * 26624 + 10240;
#pragma unroll
        for (int j = 0; j < 4; j++) {
            int cq = q0 + j * 2;
            float4 v;
            v.x = xc[(size_t)(cq * 4 + 0) * M_ + p];
            v.y = xc[(size_t)(cq * 4 + 1) * M_ + p];
            v.z = xc[(size_t)(cq * 4 + 2) * M_ + p];
            v.w = xc[(size_t)(cq * 4 + 3) * M_ + p];
            *(float4*)(bbuf + p * 128 + ((cq ^ (p & 7)) << 4)) = v;
        }
    };

    stage(0, 0); cpcommit();
    stage(1, 1); cpcommit();

    for (int i = 0; i < NC; i++) {
        cpwait1(); __syncthreads();
        int s = i % 3;
        unsigned ab = s0 + s * 26624u, bb = ab + 10240u;
#pragma unroll
        for (int kb = 0; kb < 4; kb++) {
            unsigned af[5][4], bf[4];
#pragma unroll
            for (int mf = 0; mf < 5; mf++)
                ldsm4(af[mf], a_addr(ab, mf * 16, kb, lane));
            ldsm4(bf, b_addr(bb, warp * 16, kb, lane));
#pragma unroll
            for (int mf = 0; mf < 5; mf++)
#pragma unroll
                for (int w = 0; w < 4; w++) af[mf][w] = f2tf(__uint_as_float(af[mf][w]));
#pragma unroll
            for (int w = 0; w < 4; w++) bf[w] = f2tf(__uint_as_float(bf[w]));
#pragma unroll
            for (int mf = 0; mf < 5; mf++) {
                mma8(acc[mf][0], af[mf], &bf[0]);
                mma8(acc[mf][1], af[mf], &bf[2]);
            }
        }
        if (i + 2 < NC) stage(i + 2, (i + 2) % 3);
        cpcommit();
    }

    const int g = lane >> 2, t = lane & 3;
#pragma unroll
    for (int mf = 0; mf < 5; mf++) {
#pragma unroll
        for (int nf = 0; nf < 2; nf++) {
            int col = mt * 128 + warp * 16 + nf * 8 + 2 * t;
#pragma unroll
            for (int h = 0; h < 2; h++) {
                int row = mf * 16 + g + h * 8;
                float bias = g_bqk[row];
                float2 v = make_float2(acc[mf][nf][h * 2 + 0] + bias,
                                       acc[mf][nf][h * 2 + 1] + bias);
                float* dst = (row < 16) ? &g_Q[((size_t)b * KD + row) * M_ + col]
                                        : &g_P[((size_t)b * UK + row - 16) * M_ + col];
                *(float2*)dst = v;
            }
        }
    }
}

// ---------------- k4: row softmax (unchanged) ----------------
__global__ __launch_bounds__(256) void k4_softmax() {
    __shared__ float row[M_];
    __shared__ float red[256];
    const int rid = blockIdx.x, tid = threadIdx.x;
    float* pp = g_P + (size_t)rid * M_;
    float4* p4 = (float4*)pp;
    float4* r4 = (float4*)row;

    float lmax = -3.0e38f;
#pragma unroll
    for (int i = 0; i < 4; i++) {
        float4 v = p4[tid + i * 256];
        r4[tid + i * 256] = v;
        lmax = fmaxf(lmax, fmaxf(fmaxf(v.x, v.y), fmaxf(v.z, v.w)));
    }
    red[tid] = lmax; __syncthreads();
    for (int s = 128; s > 0; s >>= 1) {
        if (tid < s) red[tid] = fmaxf(red[tid], red[tid + s]);
        __syncthreads();
    }
    const float mx = red[0];
    __syncthreads();

    float lsum = 0.f;
#pragma unroll
    for (int i = 0; i < 4; i++) {
        float4 v = r4[tid + i * 256];
        v.x = __expf(v.x - mx); v.y = __expf(v.y - mx);
        v.z = __expf(v.z - mx); v.w = __expf(v.w - mx);
        r4[tid + i * 256] = v;
        lsum += v.x + v.y + v.z + v.w;
    }
    red[tid] = lsum; __syncthreads();
    for (int s = 128; s > 0; s >>= 1) {
        if (tid < s) red[tid] += red[tid + s];
        __syncthreads();
    }
    const float inv = 1.0f / red[0];
#pragma unroll
    for (int i = 0; i < 4; i++) {
        float4 v = r4[tid + i * 256];
        v.x *= inv; v.y *= inv; v.z *= inv; v.w *= inv;
        p4[tid + i * 256] = v;
    }
}

// ---------------- k5: T = softmax(K) x^T (tf32 mma, ldmatrix) ----------------
// grid (2 n-tiles of 128, 8 k-splits of 512, B_), block 256 (8 warps 2x4).
// smem: 3 stages x (A 64x32f=8192B + B 128x32f=16384B) = 3 x 24576B.
__global__ __launch_bounds__(256, 2) void k5_T(const float* __restrict__ x) {
    extern __shared__ float smem[];
    const int nt = blockIdx.x, kz = blockIdx.y, b = blockIdx.z;
    const int tid = threadIdx.x, lane = tid & 31, warp = tid >> 5;
    const int wm = warp >> 2, wn = warp & 3;
    const float* Ag = g_P + (size_t)b * UK * M_ + kz * 512;
    const float* Bg = x + (size_t)b * C_ * M_ + (size_t)(nt * 128) * M_ + kz * 512;
    const unsigned s0 = sptr(smem);
    const int NC = 16;

    float acc[2][4][4];
#pragma unroll
    for (int i = 0; i < 2; i++)
#pragma unroll
        for (int j = 0; j < 4; j++)
#pragma unroll
            for (int r = 0; r < 4; r++) acc[i][j][r] = 0.f;

    auto stage = [&](int c, int s) {
        unsigned ab = s0 + s * 24576u;
        unsigned bb = ab + 8192u;
        const float* As = Ag + c * 32;
        const float* Bs = Bg + c * 32;
#pragma unroll
        for (int it = 0; it < 2; it++) {
            int id = tid + it * 256;
            int r = id >> 3, ch = id & 7;
            cpa16(ab + r * 128 + ((ch ^ (r & 7)) << 4), As + (size_t)r * M_ + ch * 4);
        }
#pragma unroll
        for (int it = 0; it < 4; it++) {
            int id = tid + it * 256;
            int r = id >> 3, ch = id & 7;
            cpa16(bb + r * 128 + ((ch ^ (r & 7)) << 4), Bs + (size_t)r * M_ + ch * 4);
        }
    };

    stage(0, 0); cpcommit();
    stage(1, 1); cpcommit();

    for (int i = 0; i < NC; i++) {
        cpwait1(); __syncthreads();
        int s = i % 3;
        unsigned ab = s0 + s * 24576u, bb = ab + 8192u;
#pragma unroll
        for (int kb = 0; kb < 4; kb++) {
            unsigned af[2][4], bf[2][4];
#pragma unroll
            for (int mf = 0; mf < 2; mf++)
                ldsm4(af[mf], a_addr(ab, wm * 32 + mf * 16, kb, lane));
#pragma unroll
            for (int pq = 0; pq < 2; pq++)
                ldsm4(bf[pq], b_addr(bb, wn * 32 + pq * 16, kb, lane));
#pragma unroll
            for (int mf = 0; mf < 2; mf++)
#pragma unroll
                for (int w = 0; w < 4; w++) af[mf][w] = f2tf(__uint_as_float(af[mf][w]));
#pragma unroll
            for (int pq = 0; pq < 2; pq++)
#pragma unroll
                for (int w = 0; w < 4; w++) bf[pq][w] = f2tf(__uint_as_float(bf[pq][w]));
#pragma unroll
            for (int mf = 0; mf < 2; mf++)
#pragma unroll
                for (int pq = 0; pq < 2; pq++) {
                    mma8(acc[mf][pq * 2 + 0], af[mf], &bf[pq][0]);
                    mma8(acc[mf][pq * 2 + 1], af[mf], &bf[pq][2]);
                }
        }
        if (i + 2 < NC) stage(i + 2, (i + 2) % 3);
        cpcommit();
    }

    const int g = lane >> 2, t = lane & 3;
#pragma unroll
    for (int mf = 0; mf < 2; mf++) {
        int row = wm * 32 + mf * 16 + g;
#pragma unroll
        for (int nf = 0; nf < 4; nf++) {
            int col = nt * 128 + wn * 32 + nf * 8 + 2 * t;
            atomicAdd(&g_T[((size_t)b * UK + row) * C_ + col],         acc[mf][nf][0]);
            atomicAdd(&g_T[((size_t)b * UK + row) * C_ + col + 1],     acc[mf][nf][1]);
            atomicAdd(&g_T[((size_t)b * UK + row + 8) * C_ + col],     acc[mf][nf][2]);
            atomicAdd(&g_T[((size_t)b * UK + row + 8) * C_ + col + 1], acc[mf][nf][3]);
        }
    }
}

// ---------------- k6: context (unchanged) ----------------
__global__ __launch_bounds__(256) void k6_ctx() {
    __shared__ float sT[16][C_];
    __shared__ float sW[VD][17];
    const int u = blockIdx.x, b = blockIdx.y, tid = threadIdx.x;
    const float* Tsrc = g_T + ((size_t)b * UK + u * 16) * C_;
#pragma unroll
    for (int i = 0; i < 16; i++) sT[i][tid] = Tsrc[i * C_ + tid];

    float acc[16];
#pragma unroll
    for (int i = 0; i < 16; i++) acc[i] = 0.f;
    const float* Wsrc = g_WvEff + (size_t)u * VD * C_;
    const int lr0 = tid >> 4, lc0 = tid & 15;

    for (int c0 = 0; c0 < C_; c0 += 16) {
        __syncthreads();
#pragma unroll
        for (int i = 0; i < 16; i++) {
            int r = lr0 + i * 16;
            sW[r][lc0] = Wsrc[r * C_ + c0 + lc0];
        }
        __syncthreads();
#pragma unroll
        for (int cc = 0; cc < 16; cc++) {
            float wv = sW[tid][cc];
#pragma unroll
            for (int kk = 0; kk < 16; kk++)
                acc[kk] += sT[kk][c0 + cc] * wv;
        }
    }
#pragma unroll
    for (int kk = 0; kk < 16; kk++)
        atomicAdd(&g_ctx[((size_t)b * KD + kk) * VD + tid], acc[kk]);
}

// ---------------- k7: y = Q^T ctx (unchanged) ----------------
__global__ __launch_bounds__(256) void k7_y(float* __restrict__ y) {
    __shared__ float sctx[16][VD];
    __shared__ float sQ[16][257];
    const int mt = blockIdx.x, b = blockIdx.y, tid = threadIdx.x;
    const float cbv = g_cb[tid];
#pragma unroll
    for (int i = 0; i < 16; i++)
        sctx[i][tid] = g_ctx[((size_t)b * KD + i) * VD + tid] + cbv;
    const float* Qb = g_Q + (size_t)b * KD * M_ + mt * 256;
#pragma unroll
    for (int i = 0; i < 16; i++) sQ[i][tid] = Qb[(size_t)i * M_ + tid];
    __syncthreads();

    float q[16];
#pragma unroll
    for (int i = 0; i < 16; i++) q[i] = sQ[i][tid];
    float* yb = y + (size_t)b * VD * M_ + mt * 256 + tid;
    for (int v = 0; v < VD; v += 4) {
        float4 a = make_float4(0.f, 0.f, 0.f, 0.f);
#pragma unroll
        for (int kk = 0; kk < 16; kk++) {
            const float4 cv = *(const float4*)&sctx[kk][v];
            a.x += q[kk] * cv.x; a.y += q[kk] * cv.y;
            a.z += q[kk] * cv.z; a.w += q[kk] * cv.w;
        }
        yb[(size_t)(v + 0) * M_] = a.x;
        yb[(size_t)(v + 1) * M_] = a.y;
        yb[(size_t)(v + 2) * M_] = a.z;
        yb[(size_t)(v + 3) * M_] = a.w;
    }
}

// ---------------- launch ----------------
extern "C" void kernel_launch(void* const* d_in, const int* in_sizes, int n_in,
                              void* d_out, int out_size) {
    const float* x   = (const float*)d_in[0];
    const float* Wq  = (const float*)d_in[1];
    const float* bq  = (const float*)d_in[2];
    const float* Wk  = (const float*)d_in[3];
    const float* bk  = (const float*)d_in[4];
    const float* Wv  = (const float*)d_in[5];
    const float* bv  = (const float*)d_in[6];
    const float* gq  = (const float*)d_in[7];
    const float* btq = (const float*)d_in[8];
    const float* gv  = (const float*)d_in[9];
    const float* btv = (const float*)d_in[10];
    float* y = (float*)d_out;

    cudaFuncSetAttribute(k1_gram, cudaFuncAttributeMaxDynamicSharedMemorySize, 3 * 32768);
    cudaFuncSetAttribute(k3_qk,   cudaFuncAttributeMaxDynamicSharedMemorySize, 3 * 26624);
    cudaFuncSetAttribute(k5_T,    cudaFuncAttributeMaxDynamicSharedMemorySize, 3 * 24576);

    k0_zero<<<64, 256>>>();
    k1_gram<<<dim3(3, B_, 4), 256, 3 * 32768>>>(x);
    k2_params<<<69, 256>>>(Wq, bq, Wk, bk, Wv, bv, gq, btq, gv, btv);
    k3_qk<<<dim3(32, B_), 256, 3 * 26624>>>(x);
    k4_softmax<<<B_ * UK, 256>>>();
    k5_T<<<dim3(2, 8, B_), 256, 3 * 24576>>>(x);
    k6_ctx<<<dim3(UD, B_), 256>>>();
    k7_y<<<dim3(16, B_), 256>>>(y);
}